// round 7
// baseline (speedup 1.0000x reference)
#include <cuda_runtime.h>
#include <cstdint>

#define BATCH 8
#define CCH   48
#define NPIX  4096
#define NB    32768
#define KNN   9
#define NSLOT 8              // per-slice top-k kept (8 slices/row)

// ---------------- device scratch ----------------
__device__ float  g_xt[BATCH * CCH * NPIX];  // normalized, (B,C,N) k-major
__device__ float4 g_xn[NB * 12];             // normalized, node-major (k3 exact)
__device__ float4 g_nodes[NB * 12];          // raw, node-major (k5)
__device__ float  g_sq[NB];                  // sum(xn^2)
__device__ float  g_candd[NB * 64];
__device__ int    g_candi[NB * 64];
__device__ int    g_knn[NB * KNN];
__device__ int    g_deg[NB];

// ---------------- helpers ----------------
__device__ __forceinline__ uint32_t smem_u32(const void* p) {
    uint32_t a;
    asm("{ .reg .u64 t; cvta.to.shared.u64 t, %1; cvt.u32.u64 %0, t; }" : "=r"(a) : "l"(p));
    return a;
}
__device__ __forceinline__ void cp16(uint32_t dst, const void* src) {
    asm volatile("cp.async.cg.shared.global [%0], [%1], 16;" :: "r"(dst), "l"(src));
}
__device__ __forceinline__ void cp4(uint32_t dst, const void* src) {
    asm volatile("cp.async.ca.shared.global [%0], [%1], 4;" :: "r"(dst), "l"(src));
}
__device__ __forceinline__ void cp_commit() { asm volatile("cp.async.commit_group;"); }
template <int N> __device__ __forceinline__ void cp_wait() {
    asm volatile("cp.async.wait_group %0;" :: "n"(N));
}
__device__ __forceinline__ unsigned long long ffma2(unsigned long long a,
                                                    unsigned long long b,
                                                    unsigned long long c) {
    unsigned long long d;
    asm("fma.rn.f32x2 %0, %1, %2, %3;" : "=l"(d) : "l"(a), "l"(b), "l"(c));
    return d;
}
__device__ __forceinline__ unsigned long long packdup(float x) {
    unsigned long long d;
    asm("mov.b64 %0, {%1, %1};" : "=l"(d) : "f"(x));
    return d;
}
__device__ __forceinline__ unsigned long long pack2(float x, float y) {
    unsigned long long d;
    asm("mov.b64 %0, {%1, %2};" : "=l"(d) : "f"(x), "f"(y));
    return d;
}
__device__ __forceinline__ void unpack2(unsigned long long v, float& lo, float& hi) {
    asm("mov.b64 {%0, %1}, %2;" : "=f"(lo), "=f"(hi) : "l"(v));
}

// ---------------- k2 smem layout (bytes) ----------------
#define OFF_A    0                    // 48 x 128 f32 = 24576
#define OFF_B    24576                // 2 x 24576
#define OFF_SQ   73728                // 2 x 512
#define OFF_SELD 74752                // 8 slot x 4 r x 256 tid x 4B = 32768
#define OFF_SELI 107520               // 32768
#define SMEM_K2  140288

// ======================================================================
// K1: normalize; emit g_xt (k-major), g_xn/g_nodes (node-major), sq, deg=0.
// ======================================================================
__global__ __launch_bounds__(128) void k1_normalize(const float* __restrict__ x) {
    __shared__ float s[128 * 49];
    __shared__ float s_mn[128];
    __shared__ float s_rmn[128];
    const int tid  = threadIdx.x;
    const int n0g  = blockIdx.x * 128;
    const int b    = n0g >> 12;
    const int nloc = n0g & (NPIX - 1);

    const float* xb = x + (size_t)b * CCH * NPIX + nloc;
    #pragma unroll
    for (int c = 0; c < CCH; c++)
        s[tid * 49 + c] = xb[(size_t)c * NPIX + tid];

    float ss = 0.f;
    #pragma unroll
    for (int c = 0; c < CCH; c++) { float v = s[tid * 49 + c]; ss += v * v; }
    float mn = fmaxf(sqrtf(ss), 1e-12f);
    s_mn[tid]  = mn;
    s_rmn[tid] = 1.0f / mn;
    float sqv = 0.f;
    #pragma unroll
    for (int c = 0; c < CCH; c++) { float v = s[tid * 49 + c] / mn; sqv += v * v; }
    g_sq[n0g + tid]  = sqv;
    g_deg[n0g + tid] = 0;
    __syncthreads();

    // k-major normalized (for k2 GEMM tiles), coalesced along n
    #pragma unroll
    for (int c = 0; c < CCH; c++)
        g_xt[((size_t)b * CCH + c) * NPIX + nloc + tid] = s[tid * 49 + c] * s_rmn[tid];

    // node-major exact copies (k3, k5)
    float* nodes_f = (float*)g_nodes;
    float* xn_f    = (float*)g_xn;
    #pragma unroll
    for (int it = 0; it < 48; it++) {
        int idx = it * 128 + tid;
        int q = idx / 48, rr = idx - q * 48;
        float v = s[q * 49 + rr];
        nodes_f[(size_t)n0g * 48 + idx] = v;
        xn_f[(size_t)n0g * 48 + idx]    = v / s_mn[q];
    }
}

// branchless sorted insert into 8-slot smem slice list; updates threshold
__device__ __forceinline__ void ins(float* dsel, int* isel, int tid, int r,
                                    float d, int idx, float& thr) {
    float cd = d; int ci = idx;
    #pragma unroll
    for (int s = 0; s < NSLOT; s++) {
        const int a = ((s * 4 + r) << 8) + tid;
        const float od = dsel[a]; const int oi = isel[a];
        const bool sw = cd < od;
        const float nd = sw ? cd : od; const int ni = sw ? ci : oi;
        dsel[a] = nd; isel[a] = ni;
        cd = sw ? od : cd; ci = sw ? oi : ci;
        if (s == NSLOT - 1) thr = nd;
    }
}

// ======================================================================
// K2: register-blocked fp32x2 SGEMM (128x128x48 tiles) + streaming
//     per-slice top-8 selection.  Thread = 4 rows x 16 cols (strided).
// ======================================================================
__global__ __launch_bounds__(256, 1) void k2_knn() {
    extern __shared__ __align__(16) char smem[];
    const uint32_t sb = smem_u32(smem);
    const int tid = threadIdx.x;
    const int cg  = tid & 7;          // column group (8 per row)
    const int rq  = tid >> 3;         // row quad (32)
    const int b   = blockIdx.x >> 5;
    const int rt  = blockIdx.x & 31;
    const int rowbase = b * NPIX + rt * 128;

    float* dsel = (float*)(smem + OFF_SELD);
    int*   isel = (int*)(smem + OFF_SELI);
    #pragma unroll
    for (int s = 0; s < NSLOT; s++)
        #pragma unroll
        for (int r = 0; r < 4; r++) {
            const int a = ((s * 4 + r) << 8) + tid;
            dsel[a] = __int_as_float(0x7f800000);
            isel[a] = 0x7fffffff;
        }
    float thr0 = __int_as_float(0x7f800000), thr1 = thr0, thr2 = thr0, thr3 = thr0;

    // A strip (once) + B tile 0 + sq 0
    {
        #pragma unroll
        for (int i = 0; i < 6; i++) {
            const int c = tid + i * 256;          // 1536 16B chunks
            const int k = c >> 5, p = c & 31;
            cp16(sb + OFF_A + (uint32_t)(k * 128 + p * 4) * 4,
                 g_xt + ((size_t)b * CCH + k) * NPIX + rt * 128 + p * 4);
            cp16(sb + OFF_B + (uint32_t)(k * 128 + p * 4) * 4,
                 g_xt + ((size_t)b * CCH + k) * NPIX + p * 4);
        }
        if (tid < 128) cp4(sb + OFF_SQ + tid * 4, g_sq + b * NPIX + tid);
        cp_commit();
    }

    #pragma unroll 1
    for (int t = 0; t < 32; t++) {
        const int buf = t & 1;
        cp_wait<0>();
        __syncthreads();

        if (t < 31) {
            const int col0 = (t + 1) * 128;
            const uint32_t dstB = sb + OFF_B + (buf ^ 1) * 24576;
            #pragma unroll
            for (int i = 0; i < 6; i++) {
                const int c = tid + i * 256;
                const int k = c >> 5, p = c & 31;
                cp16(dstB + (uint32_t)(k * 128 + p * 4) * 4,
                     g_xt + ((size_t)b * CCH + k) * NPIX + col0 + p * 4);
            }
            if (tid < 128) cp4(sb + OFF_SQ + (buf ^ 1) * 512 + tid * 4,
                               g_sq + b * NPIX + col0 + tid);
            cp_commit();
        }

        // ---- GEMM: C[4 rows][4 j][2 colpairs] over K=48 ----
        unsigned long long C[4][4][2];
        #pragma unroll
        for (int r = 0; r < 4; r++)
            #pragma unroll
            for (int j = 0; j < 4; j++) { C[r][j][0] = 0ull; C[r][j][1] = 0ull; }

        const char* Abase = smem + OFF_A + (uint32_t)(rq * 4) * 4;
        const char* Bbase = smem + OFF_B + buf * 24576 + (uint32_t)(cg * 4) * 4;
        #pragma unroll 8
        for (int k = 0; k < 48; k++) {
            const float4 av = *(const float4*)(Abase + k * 512);
            const unsigned long long A0 = packdup(av.x);
            const unsigned long long A1 = packdup(av.y);
            const unsigned long long A2 = packdup(av.z);
            const unsigned long long A3 = packdup(av.w);
            #pragma unroll
            for (int j = 0; j < 4; j++) {
                const float4 bv = *(const float4*)(Bbase + k * 512 + j * 128);
                const unsigned long long b01 = pack2(bv.x, bv.y);
                const unsigned long long b23 = pack2(bv.z, bv.w);
                C[0][j][0] = ffma2(A0, b01, C[0][j][0]);
                C[0][j][1] = ffma2(A0, b23, C[0][j][1]);
                C[1][j][0] = ffma2(A1, b01, C[1][j][0]);
                C[1][j][1] = ffma2(A1, b23, C[1][j][1]);
                C[2][j][0] = ffma2(A2, b01, C[2][j][0]);
                C[2][j][1] = ffma2(A2, b23, C[2][j][1]);
                C[3][j][0] = ffma2(A3, b01, C[3][j][0]);
                C[3][j][1] = ffma2(A3, b23, C[3][j][1]);
            }
        }

        // ---- epilogue: d = sq[col] - 2*dot; per-slice top-8 ----
        const int colbase = b * NPIX + t * 128;
        #pragma unroll
        for (int j = 0; j < 4; j++) {
            const float4 sqv = *(const float4*)(smem + OFF_SQ + buf * 512
                                                + (uint32_t)(j * 32 + cg * 4) * 4);
            const int gc = colbase + j * 32 + cg * 4;
            #pragma unroll
            for (int r = 0; r < 4; r++) {
                float lo, hi;
                unpack2(C[r][j][0], lo, hi);
                const float d0 = fmaf(-2.f, lo, sqv.x);
                const float d1 = fmaf(-2.f, hi, sqv.y);
                unpack2(C[r][j][1], lo, hi);
                const float d2 = fmaf(-2.f, lo, sqv.z);
                const float d3 = fmaf(-2.f, hi, sqv.w);
                float& thr = (r == 0) ? thr0 : (r == 1) ? thr1 : (r == 2) ? thr2 : thr3;
                if (d0 < thr) ins(dsel, isel, tid, r, d0, gc,     thr);
                if (d1 < thr) ins(dsel, isel, tid, r, d1, gc + 1, thr);
                if (d2 < thr) ins(dsel, isel, tid, r, d2, gc + 2, thr);
                if (d3 < thr) ins(dsel, isel, tid, r, d3, gc + 3, thr);
            }
        }
    }

    // ---- writeout: slice lists -> g_cand[row][cg][8] ----
    #pragma unroll
    for (int r = 0; r < 4; r++) {
        const int row = rowbase + rq * 4 + r;
        #pragma unroll
        for (int s = 0; s < NSLOT; s++) {
            const int a = ((s * 4 + r) << 8) + tid;
            g_candd[((size_t)row * 8 + cg) * 8 + s] = dsel[a];
            g_candi[((size_t)row * 8 + cg) * 8 + s] = isel[a];
        }
    }
}

// ======================================================================
// K3: merge 8 slices x 8 -> approx top-12 -> exact fp32 rerank ->
//     g_knn + degrees.  One 64-thread block per row.
// ======================================================================
__global__ __launch_bounds__(64) void k3_rerank() {
    const int row = blockIdx.x;
    const int t = threadIdx.x;
    __shared__ float s_row[48];
    __shared__ float s_d[64];
    __shared__ int   s_i[64];
    __shared__ float s_ed[12];
    __shared__ int   s_ei[12];

    if (t < 12) ((float4*)s_row)[t] = g_xn[(size_t)row * 12 + t];
    const float d   = g_candd[(size_t)row * 64 + t];
    const int   idx = g_candi[(size_t)row * 64 + t];
    s_d[t] = d; s_i[t] = idx;
    __syncthreads();

    int rank = 0;
    #pragma unroll 8
    for (int o = 0; o < 64; o++) {
        const float od = s_d[o]; const int oi = s_i[o];
        rank += (od < d) || (od == d && oi < idx);
    }
    if (rank < 12) {
        const float4* cv = g_xn + (size_t)idx * 12;
        float acc = 0.f;
        #pragma unroll
        for (int q = 0; q < 12; q++) {
            const float4 v = cv[q];
            acc += s_row[4 * q + 0] * v.x + s_row[4 * q + 1] * v.y
                 + s_row[4 * q + 2] * v.z + s_row[4 * q + 3] * v.w;
        }
        s_ed[rank] = fmaf(-2.f, acc, g_sq[idx]);
        s_ei[rank] = idx;
    }
    __syncthreads();

    if (t < 12) {
        const float ed = s_ed[t]; const int ei = s_ei[t];
        int r2 = 0;
        #pragma unroll
        for (int o = 0; o < 12; o++)
            r2 += (s_ed[o] < ed) || (s_ed[o] == ed && s_ei[o] < ei);
        if (r2 < KNN) {
            g_knn[(size_t)row * KNN + r2] = ei;
            if (!(row == NB - 1 && r2 == KNN - 1))
                atomicAdd(&g_deg[ei], 1);
        }
    }
}

// ======================================================================
// K5: fused Tx1 gather + both GEMMs + bias.
// ======================================================================
__global__ __launch_bounds__(192) void k5_output(const float* __restrict__ W0,
                                                 const float* __restrict__ W1,
                                                 const float* __restrict__ bias,
                                                 float* __restrict__ out) {
    const int node0 = blockIdx.x * 4;
    const int ln = threadIdx.x / 48;
    const int c  = threadIdx.x - ln * 48;
    const int i  = node0 + ln;

    __shared__ float t1[4][48];
    __shared__ int   ssrc[4][KNN];
    __shared__ float sdi[4][KNN];

    if (threadIdx.x < 4 * KNN) {
        const int l = threadIdx.x / KNN, k = threadIdx.x - l * KNN;
        const int e = (node0 + l) * KNN + k;
        const int s = g_knn[e];
        ssrc[l][k] = s;
        float di = 0.f;
        const int dg = g_deg[s];
        if (dg > 0 && e != NB * KNN - 1) di = rsqrtf((float)dg);
        sdi[l][k] = di;
    }
    __syncthreads();

    const float* nodes = (const float*)g_nodes;
    float acc = 0.f;
    #pragma unroll
    for (int k = 0; k < KNN; k++)
        acc += sdi[ln][k] * nodes[(size_t)ssrc[ln][k] * 48 + c];

    const int dgi = g_deg[i];
    const float dinv_i = (dgi > 0) ? rsqrtf((float)dgi) : 0.f;
    t1[ln][c] = -dinv_i * acc;
    __syncthreads();

    float o = bias[c];
    const float* nrow = nodes + (size_t)i * 48;
    #pragma unroll
    for (int cc = 0; cc < 48; cc++)
        o += nrow[cc] * W0[cc * 48 + c] + t1[ln][cc] * W1[cc * 48 + c];
    out[(size_t)i * 48 + c] = o;
}

// ======================================================================
extern "C" void kernel_launch(void* const* d_in, const int* in_sizes, int n_in,
                              void* d_out, int out_size) {
    const float* x    = (const float*)d_in[0];
    const float* W0   = (const float*)d_in[1];
    const float* W1   = (const float*)d_in[2];
    const float* bias = (const float*)d_in[3];
    float* out = (float*)d_out;

    cudaFuncSetAttribute(k2_knn, cudaFuncAttributeMaxDynamicSharedMemorySize, SMEM_K2);

    k1_normalize<<<NB / 128, 128>>>(x);
    k2_knn<<<BATCH * 32, 256, SMEM_K2>>>();
    k3_rerank<<<NB, 64>>>();
    k5_output<<<NB / 4, 192>>>(W0, W1, bias, out);
}